// round 14
// baseline (speedup 1.0000x reference)
#include <cuda_runtime.h>
#include <cuda_fp16.h>
#include <math.h>

#define NN 98304
#define CC 64
#define EE 1572864
#define CAP 64                  // slots per node; P(deg>64) ~ 2e-22 (guarded)
#define NTILE 16                // nodes per warp tile (m16 mma tile)
#define NGRP (NN / NTILE)       // 6144 warp work units
#define XS 72                   // smem x row stride (halfs)

// ---------------------------------------------------------------------------
// Static device scratch (zero-initialized at module load; pipeline is
// self-cleaning across graph replays: k_norm re-zeroes g_cnt, k_reset
// clears g_work/g_sum)
// ---------------------------------------------------------------------------
__device__ __align__(16) __half g_xwh[NN * CC];  // fp16: dinv*(state@W_gcn)
__device__ __align__(16) int    g_cnt[NN];
__device__ int       g_slots[NN * CAP];
__device__ float     g_conc[NN];
__device__ float     g_sum;
__device__ unsigned  g_work;

// ---------------------------------------------------------------------------
// Reset scalars (1 thread; g_cnt is zeroed by the previous replay's k_norm)
// ---------------------------------------------------------------------------
__global__ void k_reset() {
    g_sum = 0.0f;
    g_work = 0u;
}

// ---------------------------------------------------------------------------
// Bucket: fixed-capacity counting bucket, int4-vectorized edge reads
// ---------------------------------------------------------------------------
__global__ void k_bucket(const int* __restrict__ ei) {
    int t = blockIdx.x * blockDim.x + threadIdx.x;
    if (t >= EE / 4) return;
    int4 r4 = ((const int4*)ei)[t];
    int4 c4 = ((const int4*)(ei + EE))[t];
    int s;
    s = atomicAdd(&g_cnt[c4.x], 1); if (s < CAP) g_slots[(size_t)c4.x * CAP + s] = r4.x;
    s = atomicAdd(&g_cnt[c4.y], 1); if (s < CAP) g_slots[(size_t)c4.y * CAP + s] = r4.y;
    s = atomicAdd(&g_cnt[c4.z], 1); if (s < CAP) g_slots[(size_t)c4.z * CAP + s] = r4.z;
    s = atomicAdd(&g_cnt[c4.w], 1); if (s < CAP) g_slots[(size_t)c4.w * CAP + s] = r4.w;
}

// ---------------------------------------------------------------------------
// XW = dinv[row] * (state @ W_gcn), fp16 rows. Runs AFTER k_bucket.
// ---------------------------------------------------------------------------
__global__ void __launch_bounds__(256) k_gemm(const float* __restrict__ A,
                                              const float* __restrict__ W) {
    __shared__ float As[64][65];
    __shared__ float Ws[64][64];
    int tid = threadIdx.x;
    int tx = tid & 15, ty = tid >> 4;
    int rowBase = blockIdx.x * 64;

    for (int i = tid; i < 1024; i += 256) {
        float4 v = ((const float4*)W)[i];
        int k = i >> 4, c = (i & 15) << 2;
        Ws[k][c] = v.x; Ws[k][c + 1] = v.y; Ws[k][c + 2] = v.z; Ws[k][c + 3] = v.w;
    }
    for (int i = tid; i < 1024; i += 256) {
        int r = i >> 4, c = (i & 15) << 2;
        float4 v = ((const float4*)(A + (size_t)(rowBase + r) * CC))[i & 15];
        As[r][c] = v.x; As[r][c + 1] = v.y; As[r][c + 2] = v.z; As[r][c + 3] = v.w;
    }
    __syncthreads();

    float acc[4][4] = {};
    int r0 = ty * 4, c0 = tx * 4;
    #pragma unroll
    for (int k = 0; k < 64; k++) {
        float4 b = *(const float4*)&Ws[k][c0];
        #pragma unroll
        for (int i = 0; i < 4; i++) {
            float a = As[r0 + i][k];
            acc[i][0] += a * b.x; acc[i][1] += a * b.y;
            acc[i][2] += a * b.z; acc[i][3] += a * b.w;
        }
    }
    #pragma unroll
    for (int i = 0; i < 4; i++) {
        int row = rowBase + r0 + i;
        float di = rsqrtf((float)(g_cnt[row] + 1));
        __half2 h01 = __floats2half2_rn(di * acc[i][0], di * acc[i][1]);
        __half2 h23 = __floats2half2_rn(di * acc[i][2], di * acc[i][3]);
        uint2 pk = make_uint2(*(unsigned int*)&h01, *(unsigned int*)&h23);
        ((uint2*)(g_xwh + (size_t)row * CC))[tx] = pk;
    }
}

__device__ __forceinline__ void acc_u2(float4& a, uint2 u) {
    float2 f01 = __half22float2(*reinterpret_cast<__half2*>(&u.x));
    float2 f23 = __half22float2(*reinterpret_cast<__half2*>(&u.y));
    a.x += f01.x; a.y += f01.y; a.z += f23.x; a.w += f23.y;
}

// Process up to 32 edges whose src rows are spread across lanes in r.
__device__ __forceinline__ void gather_batch(float4& acc, int r, int cnt,
                                             int half, int hl) {
    const uint2* base = (const uint2*)g_xwh;
    int i = 0;
    for (; i + 8 <= cnt; i += 8) {
        unsigned r0 = (unsigned)__shfl_sync(~0u, r, i + half);
        unsigned r1 = (unsigned)__shfl_sync(~0u, r, i + 2 + half);
        unsigned r2 = (unsigned)__shfl_sync(~0u, r, i + 4 + half);
        unsigned r3 = (unsigned)__shfl_sync(~0u, r, i + 6 + half);
        uint2 u0 = base[(r0 << 4) + hl];
        uint2 u1 = base[(r1 << 4) + hl];
        uint2 u2 = base[(r2 << 4) + hl];
        uint2 u3 = base[(r3 << 4) + hl];
        __half2 ax = __hadd2(__hadd2(*(__half2*)&u0.x, *(__half2*)&u1.x),
                             __hadd2(*(__half2*)&u2.x, *(__half2*)&u3.x));
        __half2 ay = __hadd2(__hadd2(*(__half2*)&u0.y, *(__half2*)&u1.y),
                             __hadd2(*(__half2*)&u2.y, *(__half2*)&u3.y));
        float2 fx = __half22float2(ax);
        float2 fy = __half22float2(ay);
        acc.x += fx.x; acc.y += fx.y; acc.z += fy.x; acc.w += fy.y;
    }
    for (; i + 2 <= cnt; i += 2) {
        unsigned r0 = (unsigned)__shfl_sync(~0u, r, i + half);
        acc_u2(acc, base[(r0 << 4) + hl]);
    }
    if (i < cnt) {
        unsigned r0 = (unsigned)__shfl_sync(~0u, r, i);
        if (half == 0) acc_u2(acc, base[(r0 << 4) + hl]);
    }
}

__device__ __forceinline__ void mma16816(float* c, const unsigned* a,
                                         unsigned b0, unsigned b1) {
    asm volatile(
        "mma.sync.aligned.m16n8k16.row.col.f32.f16.f16.f32 "
        "{%0,%1,%2,%3}, {%4,%5,%6,%7}, {%8,%9}, {%0,%1,%2,%3};"
        : "+f"(c[0]), "+f"(c[1]), "+f"(c[2]), "+f"(c[3])
        : "r"(a[0]), "r"(a[1]), "r"(a[2]), "r"(a[3]), "r"(b0), "r"(b1));
}

// ---------------------------------------------------------------------------
// Fused: warp steals a 16-node group; gathers with cross-node slot prefetch;
// runs the m16 HMMA MLP on its own tile; accumulates conc sum.
// Forced 8 blocks/SM (32 regs) — latency-bound kernel wants max warps.
// ---------------------------------------------------------------------------
__global__ void __launch_bounds__(256, 8) k_fused(const float* __restrict__ state,
                                                  const float* __restrict__ b_gcn,
                                                  const float* __restrict__ W1,
                                                  const float* __restrict__ b1,
                                                  const float* __restrict__ W2,
                                                  const float* __restrict__ b2,
                                                  const float* __restrict__ W3,
                                                  const float* __restrict__ b3) {
    __shared__ __align__(16) __half sW1t[32 * XS];   // [n][k=64]
    __shared__ __align__(16) __half sW2t[32 * 40];   // [n][k=32]
    __shared__ float sW3[32], sB1[32], sB2[32];
    __shared__ float sb3v, sSum;
    __shared__ __align__(16) __half xs[8][NTILE * XS];   // per-warp x tiles

    int tid = threadIdx.x;
    for (int i = tid; i < 2048; i += 256) sW1t[(i & 31) * XS + (i >> 5)] = __float2half(W1[i]);
    for (int i = tid; i < 1024; i += 256) sW2t[(i & 31) * 40 + (i >> 5)] = __float2half(W2[i]);
    if (tid < 32) { sW3[tid] = W3[tid]; sB1[tid] = b1[tid]; sB2[tid] = b2[tid]; }
    if (tid == 0) { sb3v = b3[0]; sSum = 0.f; }
    __syncthreads();

    int warp = tid >> 5, lane = tid & 31;
    int half = lane >> 4, hl = lane & 15;
    int g = lane >> 2, tig = lane & 3;
    __half* xw = xs[warp];

    float4 bg = ((const float4*)b_gcn)[hl];   // loop-invariant
    float localSum = 0.f;

    for (;;) {
        unsigned grp;
        if (lane == 0) grp = atomicAdd(&g_work, 1u);
        grp = __shfl_sync(0xffffffffu, grp, 0);
        if (grp >= NGRP) break;
        int nodeBase = (int)grp * NTILE;

        // degrees for all 16 nodes (one coalesced load + shfl)
        int degAll = (lane < NTILE) ? __ldg(&g_cnt[nodeBase + lane]) : 0;

        // prefetch node 0's slot list
        int nextDeg = __shfl_sync(~0u, degAll, 0);
        int nextR = 0;
        {
            int c0 = nextDeg < 32 ? nextDeg : 32;
            if (lane < c0) nextR = __ldg(&g_slots[(size_t)nodeBase * CAP + lane]);
        }

        // ---- phase 1: gather 16 nodes into smem tile, slots prefetched ----
        for (int j = 0; j < NTILE; j++) {
            int node = nodeBase + j;
            int deg = nextDeg;
            int degc = deg < CAP ? deg : CAP;
            int r = nextR;

            if (j + 1 < NTILE) {
                nextDeg = __shfl_sync(~0u, degAll, j + 1);
                int cn = nextDeg < 32 ? nextDeg : 32;
                nextR = 0;
                if (lane < cn)
                    nextR = __ldg(&g_slots[(size_t)(node + 1) * CAP + lane]);
            }

            size_t nb = (size_t)node * CC;
            uint2 su = ((const uint2*)(g_xwh + nb))[hl];
            float4 st = ((const float4*)(state + nb))[hl];

            float4 acc = make_float4(0.f, 0.f, 0.f, 0.f);
            gather_batch(acc, r, degc < 32 ? degc : 32, half, hl);
            if (degc > 32) {                       // rare tail
                int r2 = 0;
                if (lane < degc - 32)
                    r2 = __ldg(&g_slots[(size_t)node * CAP + 32 + lane]);
                gather_batch(acc, r2, degc - 32, half, hl);
            }
            acc.x += __shfl_xor_sync(~0u, acc.x, 16);
            acc.y += __shfl_xor_sync(~0u, acc.y, 16);
            acc.z += __shfl_xor_sync(~0u, acc.z, 16);
            acc.w += __shfl_xor_sync(~0u, acc.w, 16);

            float dc = rsqrtf((float)(deg + 1));
            float2 s01 = __half22float2(*reinterpret_cast<__half2*>(&su.x));
            float2 s23 = __half22float2(*reinterpret_cast<__half2*>(&su.y));

            float xx = fmaxf(dc * (acc.x + s01.x) + bg.x, 0.f) + st.x;
            float xy = fmaxf(dc * (acc.y + s01.y) + bg.y, 0.f) + st.y;
            float xz = fmaxf(dc * (acc.z + s23.x) + bg.z, 0.f) + st.z;
            float xw2 = fmaxf(dc * (acc.w + s23.y) + bg.w, 0.f) + st.w;

            if (half == 0) {
                __half2 h01 = __floats2half2_rn(xx, xy);
                __half2 h23 = __floats2half2_rn(xz, xw2);
                uint2 pk = make_uint2(*(unsigned int*)&h01, *(unsigned int*)&h23);
                ((uint2*)(xw + j * XS))[hl] = pk;
            }
        }
        __syncwarp();

        // ---- phase 2: m16 HMMA MLP on own tile ----
        float acc1[4][4] = {};
        #pragma unroll
        for (int kt = 0; kt < 4; kt++) {
            unsigned ra[4];
            const __half* xr = xw + g * XS + kt * 16 + 2 * tig;
            ra[0] = *(const unsigned*)xr;
            ra[1] = *(const unsigned*)(xr + 8 * XS);
            ra[2] = *(const unsigned*)(xr + 8);
            ra[3] = *(const unsigned*)(xr + 8 * XS + 8);
            #pragma unroll
            for (int nt = 0; nt < 4; nt++) {
                const __half* wr = sW1t + (nt * 8 + g) * XS + kt * 16 + 2 * tig;
                mma16816(acc1[nt], ra, *(const unsigned*)wr, *(const unsigned*)(wr + 8));
            }
        }

        unsigned a2f[2][4];
        #pragma unroll
        for (int nt = 0; nt < 4; nt++) {
            float bc0 = sB1[nt * 8 + 2 * tig], bc1 = sB1[nt * 8 + 2 * tig + 1];
            float v0 = acc1[nt][0] + bc0, v1 = acc1[nt][1] + bc1;
            float v2 = acc1[nt][2] + bc0, v3 = acc1[nt][3] + bc1;
            v0 = fmaxf(v0, 0.01f * v0); v1 = fmaxf(v1, 0.01f * v1);
            v2 = fmaxf(v2, 0.01f * v2); v3 = fmaxf(v3, 0.01f * v3);
            __half2 p01 = __floats2half2_rn(v0, v1);
            __half2 p23 = __floats2half2_rn(v2, v3);
            int kt2 = nt >> 1, hi = nt & 1;
            a2f[kt2][hi ? 2 : 0] = *(unsigned*)&p01;
            a2f[kt2][hi ? 3 : 1] = *(unsigned*)&p23;
        }

        float acc2[4][4] = {};
        #pragma unroll
        for (int kt = 0; kt < 2; kt++) {
            #pragma unroll
            for (int nt = 0; nt < 4; nt++) {
                const __half* wr = sW2t + (nt * 8 + g) * 40 + kt * 16 + 2 * tig;
                mma16816(acc2[nt], a2f[kt], *(const unsigned*)wr, *(const unsigned*)(wr + 8));
            }
        }

        float p0 = 0.f, p1 = 0.f;
        #pragma unroll
        for (int nt = 0; nt < 4; nt++) {
            float bc0 = sB2[nt * 8 + 2 * tig], bc1 = sB2[nt * 8 + 2 * tig + 1];
            float w0 = sW3[nt * 8 + 2 * tig], w1 = sW3[nt * 8 + 2 * tig + 1];
            float c0 = acc2[nt][0] + bc0; c0 = fmaxf(c0, 0.01f * c0);
            float c1 = acc2[nt][1] + bc1; c1 = fmaxf(c1, 0.01f * c1);
            float c2 = acc2[nt][2] + bc0; c2 = fmaxf(c2, 0.01f * c2);
            float c3 = acc2[nt][3] + bc1; c3 = fmaxf(c3, 0.01f * c3);
            p0 += c0 * w0 + c1 * w1;
            p1 += c2 * w0 + c3 * w1;
        }
        p0 += __shfl_xor_sync(~0u, p0, 1); p0 += __shfl_xor_sync(~0u, p0, 2);
        p1 += __shfl_xor_sync(~0u, p1, 1); p1 += __shfl_xor_sync(~0u, p1, 2);
        if (tig == 0) {
            float z0 = p0 + sb3v;
            float c0v = (z0 > 20.f) ? z0 : log1pf(expf(z0));
            float z1 = p1 + sb3v;
            float c1v = (z1 > 20.f) ? z1 : log1pf(expf(z1));
            g_conc[nodeBase + g] = c0v;
            g_conc[nodeBase + g + 8] = c1v;
            localSum += c0v + c1v;
        }
        __syncwarp();   // xs reuse next iteration
    }

    localSum += __shfl_xor_sync(~0u, localSum, 1);
    localSum += __shfl_xor_sync(~0u, localSum, 2);
    localSum += __shfl_xor_sync(~0u, localSum, 4);
    localSum += __shfl_xor_sync(~0u, localSum, 8);
    localSum += __shfl_xor_sync(~0u, localSum, 16);
    if (lane == 0) atomicAdd(&sSum, localSum);
    __syncthreads();
    if (tid == 0) atomicAdd(&g_sum, sSum);
}

// ---------------------------------------------------------------------------
// action = conc / (sum + 1e-20); also re-zero g_cnt for the next replay
// (self-cleaning graph: runs after k_fused, before next replay's k_bucket)
// ---------------------------------------------------------------------------
__global__ void k_norm(float* __restrict__ out) {
    int i = blockIdx.x * blockDim.x + threadIdx.x;
    if (i < NN / 4) {
        float inv = 1.0f / (g_sum + 1e-20f);
        float4 c = ((const float4*)g_conc)[i];
        ((float4*)out)[i] = make_float4(c.x * inv, c.y * inv, c.z * inv, c.w * inv);
        ((int4*)g_cnt)[i] = make_int4(0, 0, 0, 0);
    }
}

extern "C" void kernel_launch(void* const* d_in, const int* in_sizes, int n_in,
                              void* d_out, int out_size) {
    const float* state = (const float*)d_in[0];
    const int*   ei    = (const int*)d_in[1];
    const float* W_gcn = (const float*)d_in[2];
    const float* b_gcn = (const float*)d_in[3];
    const float* W1 = (const float*)d_in[4];
    const float* b1 = (const float*)d_in[5];
    const float* W2 = (const float*)d_in[6];
    const float* b2 = (const float*)d_in[7];
    const float* W3 = (const float*)d_in[8];
    const float* b3 = (const float*)d_in[9];
    float* out = (float*)d_out;

    k_reset<<<1, 1>>>();
    k_bucket<<<(EE / 4 + 255) / 256, 256>>>(ei);
    k_gemm<<<NN / 64, 256>>>(state, W_gcn);
    k_fused<<<1184, 256>>>(state, b_gcn, W1, b1, W2, b2, W3, b3);
    k_norm<<<NN / 4 / 256, 256>>>(out);
}

// round 15
// speedup vs baseline: 1.1878x; 1.1878x over previous
#include <cuda_runtime.h>
#include <cuda_fp16.h>
#include <math.h>

#define NN 98304
#define CC 64
#define EE 1572864
#define CAP 64                  // slots per node; P(deg>64) ~ 2e-22 (guarded)
#define NTILE 16                // nodes per warp tile (m16 mma tile)
#define NGRP (NN / NTILE)       // 6144 warp work units
#define XS 72                   // smem x row stride (halfs)

// ---------------------------------------------------------------------------
// Static device scratch (zero-initialized at module load; pipeline is
// self-cleaning across graph replays: k_norm re-zeroes g_cnt, k_gemm
// clears g_work/g_sum before k_fused consumes them)
// ---------------------------------------------------------------------------
__device__ __align__(16) __half g_xwh[NN * CC];  // fp16: dinv*(state@W_gcn)
__device__ __align__(16) int    g_cnt[NN];
__device__ int       g_slots[NN * CAP];
__device__ float     g_conc[NN];
__device__ float     g_sum;
__device__ unsigned  g_work;

// ---------------------------------------------------------------------------
// Bucket: fixed-capacity counting bucket, int4-vectorized edge reads
// ---------------------------------------------------------------------------
__global__ void k_bucket(const int* __restrict__ ei) {
    int t = blockIdx.x * blockDim.x + threadIdx.x;
    if (t >= EE / 4) return;
    int4 r4 = ((const int4*)ei)[t];
    int4 c4 = ((const int4*)(ei + EE))[t];
    int s;
    s = atomicAdd(&g_cnt[c4.x], 1); if (s < CAP) g_slots[(size_t)c4.x * CAP + s] = r4.x;
    s = atomicAdd(&g_cnt[c4.y], 1); if (s < CAP) g_slots[(size_t)c4.y * CAP + s] = r4.y;
    s = atomicAdd(&g_cnt[c4.z], 1); if (s < CAP) g_slots[(size_t)c4.z * CAP + s] = r4.z;
    s = atomicAdd(&g_cnt[c4.w], 1); if (s < CAP) g_slots[(size_t)c4.w * CAP + s] = r4.w;
}

// ---------------------------------------------------------------------------
// XW = dinv[row] * (state @ W_gcn), fp16 rows. Runs AFTER k_bucket.
// Also resets g_work/g_sum for the downstream k_fused (one thread).
// ---------------------------------------------------------------------------
__global__ void __launch_bounds__(256) k_gemm(const float* __restrict__ A,
                                              const float* __restrict__ W) {
    __shared__ float As[64][65];
    __shared__ float Ws[64][64];
    int tid = threadIdx.x;
    int tx = tid & 15, ty = tid >> 4;
    int rowBase = blockIdx.x * 64;

    if (blockIdx.x == 0 && tid == 0) { g_sum = 0.0f; g_work = 0u; }

    for (int i = tid; i < 1024; i += 256) {
        float4 v = ((const float4*)W)[i];
        int k = i >> 4, c = (i & 15) << 2;
        Ws[k][c] = v.x; Ws[k][c + 1] = v.y; Ws[k][c + 2] = v.z; Ws[k][c + 3] = v.w;
    }
    for (int i = tid; i < 1024; i += 256) {
        int r = i >> 4, c = (i & 15) << 2;
        float4 v = ((const float4*)(A + (size_t)(rowBase + r) * CC))[i & 15];
        As[r][c] = v.x; As[r][c + 1] = v.y; As[r][c + 2] = v.z; As[r][c + 3] = v.w;
    }
    __syncthreads();

    float acc[4][4] = {};
    int r0 = ty * 4, c0 = tx * 4;
    #pragma unroll
    for (int k = 0; k < 64; k++) {
        float4 b = *(const float4*)&Ws[k][c0];
        #pragma unroll
        for (int i = 0; i < 4; i++) {
            float a = As[r0 + i][k];
            acc[i][0] += a * b.x; acc[i][1] += a * b.y;
            acc[i][2] += a * b.z; acc[i][3] += a * b.w;
        }
    }
    #pragma unroll
    for (int i = 0; i < 4; i++) {
        int row = rowBase + r0 + i;
        float di = rsqrtf((float)(g_cnt[row] + 1));
        __half2 h01 = __floats2half2_rn(di * acc[i][0], di * acc[i][1]);
        __half2 h23 = __floats2half2_rn(di * acc[i][2], di * acc[i][3]);
        uint2 pk = make_uint2(*(unsigned int*)&h01, *(unsigned int*)&h23);
        ((uint2*)(g_xwh + (size_t)row * CC))[tx] = pk;
    }
}

__device__ __forceinline__ void acc_u2(float4& a, uint2 u) {
    float2 f01 = __half22float2(*reinterpret_cast<__half2*>(&u.x));
    float2 f23 = __half22float2(*reinterpret_cast<__half2*>(&u.y));
    a.x += f01.x; a.y += f01.y; a.z += f23.x; a.w += f23.y;
}

// Process up to 32 edges whose src rows are spread across lanes in r.
__device__ __forceinline__ void gather_batch(float4& acc, int r, int cnt,
                                             int half, int hl) {
    const uint2* base = (const uint2*)g_xwh;
    int i = 0;
    for (; i + 8 <= cnt; i += 8) {
        unsigned r0 = (unsigned)__shfl_sync(~0u, r, i + half);
        unsigned r1 = (unsigned)__shfl_sync(~0u, r, i + 2 + half);
        unsigned r2 = (unsigned)__shfl_sync(~0u, r, i + 4 + half);
        unsigned r3 = (unsigned)__shfl_sync(~0u, r, i + 6 + half);
        uint2 u0 = base[(r0 << 4) + hl];
        uint2 u1 = base[(r1 << 4) + hl];
        uint2 u2 = base[(r2 << 4) + hl];
        uint2 u3 = base[(r3 << 4) + hl];
        __half2 ax = __hadd2(__hadd2(*(__half2*)&u0.x, *(__half2*)&u1.x),
                             __hadd2(*(__half2*)&u2.x, *(__half2*)&u3.x));
        __half2 ay = __hadd2(__hadd2(*(__half2*)&u0.y, *(__half2*)&u1.y),
                             __hadd2(*(__half2*)&u2.y, *(__half2*)&u3.y));
        float2 fx = __half22float2(ax);
        float2 fy = __half22float2(ay);
        acc.x += fx.x; acc.y += fx.y; acc.z += fy.x; acc.w += fy.y;
    }
    for (; i + 2 <= cnt; i += 2) {
        unsigned r0 = (unsigned)__shfl_sync(~0u, r, i + half);
        acc_u2(acc, base[(r0 << 4) + hl]);
    }
    if (i < cnt) {
        unsigned r0 = (unsigned)__shfl_sync(~0u, r, i);
        if (half == 0) acc_u2(acc, base[(r0 << 4) + hl]);
    }
}

__device__ __forceinline__ void mma16816(float* c, const unsigned* a,
                                         unsigned b0, unsigned b1) {
    asm volatile(
        "mma.sync.aligned.m16n8k16.row.col.f32.f16.f16.f32 "
        "{%0,%1,%2,%3}, {%4,%5,%6,%7}, {%8,%9}, {%0,%1,%2,%3};"
        : "+f"(c[0]), "+f"(c[1]), "+f"(c[2]), "+f"(c[3])
        : "r"(a[0]), "r"(a[1]), "r"(a[2]), "r"(a[3]), "r"(b0), "r"(b1));
}

// ---------------------------------------------------------------------------
// Fused: warp steals a 16-node group; gathers with cross-node slot prefetch;
// runs the m16 HMMA MLP on its own tile; accumulates conc sum.
// Plain launch bounds: 40 regs / 6 blocks/SM measured best (R12); forcing
// 8 blocks/SM spilled and regressed (R14).
// ---------------------------------------------------------------------------
__global__ void __launch_bounds__(256) k_fused(const float* __restrict__ state,
                                               const float* __restrict__ b_gcn,
                                               const float* __restrict__ W1,
                                               const float* __restrict__ b1,
                                               const float* __restrict__ W2,
                                               const float* __restrict__ b2,
                                               const float* __restrict__ W3,
                                               const float* __restrict__ b3) {
    __shared__ __align__(16) __half sW1t[32 * XS];   // [n][k=64]
    __shared__ __align__(16) __half sW2t[32 * 40];   // [n][k=32]
    __shared__ float sW3[32], sB1[32], sB2[32];
    __shared__ float sb3v, sSum;
    __shared__ __align__(16) __half xs[8][NTILE * XS];   // per-warp x tiles

    int tid = threadIdx.x;
    for (int i = tid; i < 2048; i += 256) sW1t[(i & 31) * XS + (i >> 5)] = __float2half(W1[i]);
    for (int i = tid; i < 1024; i += 256) sW2t[(i & 31) * 40 + (i >> 5)] = __float2half(W2[i]);
    if (tid < 32) { sW3[tid] = W3[tid]; sB1[tid] = b1[tid]; sB2[tid] = b2[tid]; }
    if (tid == 0) { sb3v = b3[0]; sSum = 0.f; }
    __syncthreads();

    int warp = tid >> 5, lane = tid & 31;
    int half = lane >> 4, hl = lane & 15;
    int g = lane >> 2, tig = lane & 3;
    __half* xw = xs[warp];

    float4 bg = ((const float4*)b_gcn)[hl];   // loop-invariant
    float localSum = 0.f;

    for (;;) {
        unsigned grp;
        if (lane == 0) grp = atomicAdd(&g_work, 1u);
        grp = __shfl_sync(0xffffffffu, grp, 0);
        if (grp >= NGRP) break;
        int nodeBase = (int)grp * NTILE;

        // degrees for all 16 nodes (one coalesced load + shfl)
        int degAll = (lane < NTILE) ? __ldg(&g_cnt[nodeBase + lane]) : 0;

        // prefetch node 0's slot list
        int nextDeg = __shfl_sync(~0u, degAll, 0);
        int nextR = 0;
        {
            int c0 = nextDeg < 32 ? nextDeg : 32;
            if (lane < c0) nextR = __ldg(&g_slots[(size_t)nodeBase * CAP + lane]);
        }

        // ---- phase 1: gather 16 nodes into smem tile, slots prefetched ----
        for (int j = 0; j < NTILE; j++) {
            int node = nodeBase + j;
            int deg = nextDeg;
            int degc = deg < CAP ? deg : CAP;
            int r = nextR;

            if (j + 1 < NTILE) {
                nextDeg = __shfl_sync(~0u, degAll, j + 1);
                int cn = nextDeg < 32 ? nextDeg : 32;
                nextR = 0;
                if (lane < cn)
                    nextR = __ldg(&g_slots[(size_t)(node + 1) * CAP + lane]);
            }

            size_t nb = (size_t)node * CC;
            uint2 su = ((const uint2*)(g_xwh + nb))[hl];
            float4 st = ((const float4*)(state + nb))[hl];

            float4 acc = make_float4(0.f, 0.f, 0.f, 0.f);
            gather_batch(acc, r, degc < 32 ? degc : 32, half, hl);
            if (degc > 32) {                       // rare tail
                int r2 = 0;
                if (lane < degc - 32)
                    r2 = __ldg(&g_slots[(size_t)node * CAP + 32 + lane]);
                gather_batch(acc, r2, degc - 32, half, hl);
            }
            acc.x += __shfl_xor_sync(~0u, acc.x, 16);
            acc.y += __shfl_xor_sync(~0u, acc.y, 16);
            acc.z += __shfl_xor_sync(~0u, acc.z, 16);
            acc.w += __shfl_xor_sync(~0u, acc.w, 16);

            float dc = rsqrtf((float)(deg + 1));
            float2 s01 = __half22float2(*reinterpret_cast<__half2*>(&su.x));
            float2 s23 = __half22float2(*reinterpret_cast<__half2*>(&su.y));

            float xx = fmaxf(dc * (acc.x + s01.x) + bg.x, 0.f) + st.x;
            float xy = fmaxf(dc * (acc.y + s01.y) + bg.y, 0.f) + st.y;
            float xz = fmaxf(dc * (acc.z + s23.x) + bg.z, 0.f) + st.z;
            float xw2 = fmaxf(dc * (acc.w + s23.y) + bg.w, 0.f) + st.w;

            if (half == 0) {
                __half2 h01 = __floats2half2_rn(xx, xy);
                __half2 h23 = __floats2half2_rn(xz, xw2);
                uint2 pk = make_uint2(*(unsigned int*)&h01, *(unsigned int*)&h23);
                ((uint2*)(xw + j * XS))[hl] = pk;
            }
        }
        __syncwarp();

        // ---- phase 2: m16 HMMA MLP on own tile ----
        float acc1[4][4] = {};
        #pragma unroll
        for (int kt = 0; kt < 4; kt++) {
            unsigned ra[4];
            const __half* xr = xw + g * XS + kt * 16 + 2 * tig;
            ra[0] = *(const unsigned*)xr;
            ra[1] = *(const unsigned*)(xr + 8 * XS);
            ra[2] = *(const unsigned*)(xr + 8);
            ra[3] = *(const unsigned*)(xr + 8 * XS + 8);
            #pragma unroll
            for (int nt = 0; nt < 4; nt++) {
                const __half* wr = sW1t + (nt * 8 + g) * XS + kt * 16 + 2 * tig;
                mma16816(acc1[nt], ra, *(const unsigned*)wr, *(const unsigned*)(wr + 8));
            }
        }

        unsigned a2f[2][4];
        #pragma unroll
        for (int nt = 0; nt < 4; nt++) {
            float bc0 = sB1[nt * 8 + 2 * tig], bc1 = sB1[nt * 8 + 2 * tig + 1];
            float v0 = acc1[nt][0] + bc0, v1 = acc1[nt][1] + bc1;
            float v2 = acc1[nt][2] + bc0, v3 = acc1[nt][3] + bc1;
            v0 = fmaxf(v0, 0.01f * v0); v1 = fmaxf(v1, 0.01f * v1);
            v2 = fmaxf(v2, 0.01f * v2); v3 = fmaxf(v3, 0.01f * v3);
            __half2 p01 = __floats2half2_rn(v0, v1);
            __half2 p23 = __floats2half2_rn(v2, v3);
            int kt2 = nt >> 1, hi = nt & 1;
            a2f[kt2][hi ? 2 : 0] = *(unsigned*)&p01;
            a2f[kt2][hi ? 3 : 1] = *(unsigned*)&p23;
        }

        float acc2[4][4] = {};
        #pragma unroll
        for (int kt = 0; kt < 2; kt++) {
            #pragma unroll
            for (int nt = 0; nt < 4; nt++) {
                const __half* wr = sW2t + (nt * 8 + g) * 40 + kt * 16 + 2 * tig;
                mma16816(acc2[nt], a2f[kt], *(const unsigned*)wr, *(const unsigned*)(wr + 8));
            }
        }

        float p0 = 0.f, p1 = 0.f;
        #pragma unroll
        for (int nt = 0; nt < 4; nt++) {
            float bc0 = sB2[nt * 8 + 2 * tig], bc1 = sB2[nt * 8 + 2 * tig + 1];
            float w0 = sW3[nt * 8 + 2 * tig], w1 = sW3[nt * 8 + 2 * tig + 1];
            float c0 = acc2[nt][0] + bc0; c0 = fmaxf(c0, 0.01f * c0);
            float c1 = acc2[nt][1] + bc1; c1 = fmaxf(c1, 0.01f * c1);
            float c2 = acc2[nt][2] + bc0; c2 = fmaxf(c2, 0.01f * c2);
            float c3 = acc2[nt][3] + bc1; c3 = fmaxf(c3, 0.01f * c3);
            p0 += c0 * w0 + c1 * w1;
            p1 += c2 * w0 + c3 * w1;
        }
        p0 += __shfl_xor_sync(~0u, p0, 1); p0 += __shfl_xor_sync(~0u, p0, 2);
        p1 += __shfl_xor_sync(~0u, p1, 1); p1 += __shfl_xor_sync(~0u, p1, 2);
        if (tig == 0) {
            float z0 = p0 + sb3v;
            float c0v = (z0 > 20.f) ? z0 : log1pf(expf(z0));
            float z1 = p1 + sb3v;
            float c1v = (z1 > 20.f) ? z1 : log1pf(expf(z1));
            g_conc[nodeBase + g] = c0v;
            g_conc[nodeBase + g + 8] = c1v;
            localSum += c0v + c1v;
        }
        __syncwarp();   // xs reuse next iteration
    }

    localSum += __shfl_xor_sync(~0u, localSum, 1);
    localSum += __shfl_xor_sync(~0u, localSum, 2);
    localSum += __shfl_xor_sync(~0u, localSum, 4);
    localSum += __shfl_xor_sync(~0u, localSum, 8);
    localSum += __shfl_xor_sync(~0u, localSum, 16);
    if (lane == 0) atomicAdd(&sSum, localSum);
    __syncthreads();
    if (tid == 0) atomicAdd(&g_sum, sSum);
}

// ---------------------------------------------------------------------------
// action = conc / (sum + 1e-20); also re-zero g_cnt for the next replay
// ---------------------------------------------------------------------------
__global__ void k_norm(float* __restrict__ out) {
    int i = blockIdx.x * blockDim.x + threadIdx.x;
    if (i < NN / 4) {
        float inv = 1.0f / (g_sum + 1e-20f);
        float4 c = ((const float4*)g_conc)[i];
        ((float4*)out)[i] = make_float4(c.x * inv, c.y * inv, c.z * inv, c.w * inv);
        ((int4*)g_cnt)[i] = make_int4(0, 0, 0, 0);
    }
}

extern "C" void kernel_launch(void* const* d_in, const int* in_sizes, int n_in,
                              void* d_out, int out_size) {
    const float* state = (const float*)d_in[0];
    const int*   ei    = (const int*)d_in[1];
    const float* W_gcn = (const float*)d_in[2];
    const float* b_gcn = (const float*)d_in[3];
    const float* W1 = (const float*)d_in[4];
    const float* b1 = (const float*)d_in[5];
    const float* W2 = (const float*)d_in[6];
    const float* b2 = (const float*)d_in[7];
    const float* W3 = (const float*)d_in[8];
    const float* b3 = (const float*)d_in[9];
    float* out = (float*)d_out;

    k_bucket<<<(EE / 4 + 255) / 256, 256>>>(ei);
    k_gemm<<<NN / 64, 256>>>(state, W_gcn);
    k_fused<<<1184, 256>>>(state, b_gcn, W1, b1, W2, b2, W3, b3);
    k_norm<<<NN / 4 / 256, 256>>>(out);
}

// round 16
// speedup vs baseline: 1.2040x; 1.0136x over previous
#include <cuda_runtime.h>
#include <cuda_fp16.h>
#include <math.h>

#define NN 98304
#define CC 64
#define EE 1572864
#define CAP 64                  // slots per node; P(deg>64) ~ 2e-22 (guarded)
#define NTILE 16                // nodes per warp tile (m16 mma tile)
#define NGRP (NN / NTILE)       // 6144 warp work units
#define XS 72                   // smem x row stride (halfs)

// ---------------------------------------------------------------------------
// Static device scratch (zero-initialized at module load; pipeline is
// self-cleaning across graph replays: k_norm re-zeroes g_cnt, k_gemm
// clears g_work/g_sum before k_fused consumes them)
// ---------------------------------------------------------------------------
__device__ __align__(16) __half g_xwh[NN * CC];  // fp16: dinv*(state@W_gcn)
__device__ __align__(16) int    g_cnt[NN];
__device__ int       g_slots[NN * CAP];
__device__ float     g_conc[NN];
__device__ float     g_sum;
__device__ unsigned  g_work;

// ---------------------------------------------------------------------------
// Bucket: fixed-capacity counting bucket, int4-vectorized edge reads
// ---------------------------------------------------------------------------
__global__ void k_bucket(const int* __restrict__ ei) {
    int t = blockIdx.x * blockDim.x + threadIdx.x;
    if (t >= EE / 4) return;
    int4 r4 = ((const int4*)ei)[t];
    int4 c4 = ((const int4*)(ei + EE))[t];
    int s;
    s = atomicAdd(&g_cnt[c4.x], 1); if (s < CAP) g_slots[(size_t)c4.x * CAP + s] = r4.x;
    s = atomicAdd(&g_cnt[c4.y], 1); if (s < CAP) g_slots[(size_t)c4.y * CAP + s] = r4.y;
    s = atomicAdd(&g_cnt[c4.z], 1); if (s < CAP) g_slots[(size_t)c4.z * CAP + s] = r4.z;
    s = atomicAdd(&g_cnt[c4.w], 1); if (s < CAP) g_slots[(size_t)c4.w * CAP + s] = r4.w;
}

// ---------------------------------------------------------------------------
// XW = dinv[row] * (state @ W_gcn), fp16 rows. Runs AFTER k_bucket.
// Also resets g_work/g_sum for the downstream k_fused (one thread).
// ---------------------------------------------------------------------------
__global__ void __launch_bounds__(256) k_gemm(const float* __restrict__ A,
                                              const float* __restrict__ W) {
    __shared__ float As[64][65];
    __shared__ float Ws[64][64];
    int tid = threadIdx.x;
    int tx = tid & 15, ty = tid >> 4;
    int rowBase = blockIdx.x * 64;

    if (blockIdx.x == 0 && tid == 0) { g_sum = 0.0f; g_work = 0u; }

    for (int i = tid; i < 1024; i += 256) {
        float4 v = ((const float4*)W)[i];
        int k = i >> 4, c = (i & 15) << 2;
        Ws[k][c] = v.x; Ws[k][c + 1] = v.y; Ws[k][c + 2] = v.z; Ws[k][c + 3] = v.w;
    }
    for (int i = tid; i < 1024; i += 256) {
        int r = i >> 4, c = (i & 15) << 2;
        float4 v = ((const float4*)(A + (size_t)(rowBase + r) * CC))[i & 15];
        As[r][c] = v.x; As[r][c + 1] = v.y; As[r][c + 2] = v.z; As[r][c + 3] = v.w;
    }
    __syncthreads();

    float acc[4][4] = {};
    int r0 = ty * 4, c0 = tx * 4;
    #pragma unroll
    for (int k = 0; k < 64; k++) {
        float4 b = *(const float4*)&Ws[k][c0];
        #pragma unroll
        for (int i = 0; i < 4; i++) {
            float a = As[r0 + i][k];
            acc[i][0] += a * b.x; acc[i][1] += a * b.y;
            acc[i][2] += a * b.z; acc[i][3] += a * b.w;
        }
    }
    #pragma unroll
    for (int i = 0; i < 4; i++) {
        int row = rowBase + r0 + i;
        float di = rsqrtf((float)(g_cnt[row] + 1));
        __half2 h01 = __floats2half2_rn(di * acc[i][0], di * acc[i][1]);
        __half2 h23 = __floats2half2_rn(di * acc[i][2], di * acc[i][3]);
        uint2 pk = make_uint2(*(unsigned int*)&h01, *(unsigned int*)&h23);
        ((uint2*)(g_xwh + (size_t)row * CC))[tx] = pk;
    }
}

__device__ __forceinline__ void acc_u2(float4& a, uint2 u) {
    float2 f01 = __half22float2(*reinterpret_cast<__half2*>(&u.x));
    float2 f23 = __half22float2(*reinterpret_cast<__half2*>(&u.y));
    a.x += f01.x; a.y += f01.y; a.z += f23.x; a.w += f23.y;
}

// Process up to 32 edges whose src rows are spread across lanes in r.
// 16-edge path keeps 8 LDGs in flight per half-warp step (latency coverage).
__device__ __forceinline__ void gather_batch(float4& acc, int r, int cnt,
                                             int half, int hl) {
    const uint2* base = (const uint2*)g_xwh;
    int i = 0;
    for (; i + 16 <= cnt; i += 16) {
        unsigned r0 = (unsigned)__shfl_sync(~0u, r, i + half);
        unsigned r1 = (unsigned)__shfl_sync(~0u, r, i + 2 + half);
        unsigned r2 = (unsigned)__shfl_sync(~0u, r, i + 4 + half);
        unsigned r3 = (unsigned)__shfl_sync(~0u, r, i + 6 + half);
        unsigned r4 = (unsigned)__shfl_sync(~0u, r, i + 8 + half);
        unsigned r5 = (unsigned)__shfl_sync(~0u, r, i + 10 + half);
        unsigned r6 = (unsigned)__shfl_sync(~0u, r, i + 12 + half);
        unsigned r7 = (unsigned)__shfl_sync(~0u, r, i + 14 + half);
        uint2 u0 = base[(r0 << 4) + hl];
        uint2 u1 = base[(r1 << 4) + hl];
        uint2 u2 = base[(r2 << 4) + hl];
        uint2 u3 = base[(r3 << 4) + hl];
        uint2 u4 = base[(r4 << 4) + hl];
        uint2 u5 = base[(r5 << 4) + hl];
        uint2 u6 = base[(r6 << 4) + hl];
        uint2 u7 = base[(r7 << 4) + hl];
        __half2 ax = __hadd2(
            __hadd2(__hadd2(*(__half2*)&u0.x, *(__half2*)&u1.x),
                    __hadd2(*(__half2*)&u2.x, *(__half2*)&u3.x)),
            __hadd2(__hadd2(*(__half2*)&u4.x, *(__half2*)&u5.x),
                    __hadd2(*(__half2*)&u6.x, *(__half2*)&u7.x)));
        __half2 ay = __hadd2(
            __hadd2(__hadd2(*(__half2*)&u0.y, *(__half2*)&u1.y),
                    __hadd2(*(__half2*)&u2.y, *(__half2*)&u3.y)),
            __hadd2(__hadd2(*(__half2*)&u4.y, *(__half2*)&u5.y),
                    __hadd2(*(__half2*)&u6.y, *(__half2*)&u7.y)));
        float2 fx = __half22float2(ax);
        float2 fy = __half22float2(ay);
        acc.x += fx.x; acc.y += fx.y; acc.z += fy.x; acc.w += fy.y;
    }
    for (; i + 8 <= cnt; i += 8) {
        unsigned r0 = (unsigned)__shfl_sync(~0u, r, i + half);
        unsigned r1 = (unsigned)__shfl_sync(~0u, r, i + 2 + half);
        unsigned r2 = (unsigned)__shfl_sync(~0u, r, i + 4 + half);
        unsigned r3 = (unsigned)__shfl_sync(~0u, r, i + 6 + half);
        uint2 u0 = base[(r0 << 4) + hl];
        uint2 u1 = base[(r1 << 4) + hl];
        uint2 u2 = base[(r2 << 4) + hl];
        uint2 u3 = base[(r3 << 4) + hl];
        __half2 ax = __hadd2(__hadd2(*(__half2*)&u0.x, *(__half2*)&u1.x),
                             __hadd2(*(__half2*)&u2.x, *(__half2*)&u3.x));
        __half2 ay = __hadd2(__hadd2(*(__half2*)&u0.y, *(__half2*)&u1.y),
                             __hadd2(*(__half2*)&u2.y, *(__half2*)&u3.y));
        float2 fx = __half22float2(ax);
        float2 fy = __half22float2(ay);
        acc.x += fx.x; acc.y += fx.y; acc.z += fy.x; acc.w += fy.y;
    }
    for (; i + 2 <= cnt; i += 2) {
        unsigned r0 = (unsigned)__shfl_sync(~0u, r, i + half);
        acc_u2(acc, base[(r0 << 4) + hl]);
    }
    if (i < cnt) {
        unsigned r0 = (unsigned)__shfl_sync(~0u, r, i);
        if (half == 0) acc_u2(acc, base[(r0 << 4) + hl]);
    }
}

__device__ __forceinline__ void mma16816(float* c, const unsigned* a,
                                         unsigned b0, unsigned b1) {
    asm volatile(
        "mma.sync.aligned.m16n8k16.row.col.f32.f16.f16.f32 "
        "{%0,%1,%2,%3}, {%4,%5,%6,%7}, {%8,%9}, {%0,%1,%2,%3};"
        : "+f"(c[0]), "+f"(c[1]), "+f"(c[2]), "+f"(c[3])
        : "r"(a[0]), "r"(a[1]), "r"(a[2]), "r"(a[3]), "r"(b0), "r"(b1));
}

// ---------------------------------------------------------------------------
// Fused: warp steals a 16-node group; gathers with cross-node slot prefetch
// and a 16-edge-deep load pipeline; runs the m16 HMMA MLP on its own tile.
// Plain launch bounds: 40-48 regs / 5-6 blocks/SM (R14: forcing 8 spilled).
// ---------------------------------------------------------------------------
__global__ void __launch_bounds__(256) k_fused(const float* __restrict__ state,
                                               const float* __restrict__ b_gcn,
                                               const float* __restrict__ W1,
                                               const float* __restrict__ b1,
                                               const float* __restrict__ W2,
                                               const float* __restrict__ b2,
                                               const float* __restrict__ W3,
                                               const float* __restrict__ b3) {
    __shared__ __align__(16) __half sW1t[32 * XS];   // [n][k=64]
    __shared__ __align__(16) __half sW2t[32 * 40];   // [n][k=32]
    __shared__ float sW3[32], sB1[32], sB2[32];
    __shared__ float sb3v, sSum;
    __shared__ __align__(16) __half xs[8][NTILE * XS];   // per-warp x tiles

    int tid = threadIdx.x;
    for (int i = tid; i < 2048; i += 256) sW1t[(i & 31) * XS + (i >> 5)] = __float2half(W1[i]);
    for (int i = tid; i < 1024; i += 256) sW2t[(i & 31) * 40 + (i >> 5)] = __float2half(W2[i]);
    if (tid < 32) { sW3[tid] = W3[tid]; sB1[tid] = b1[tid]; sB2[tid] = b2[tid]; }
    if (tid == 0) { sb3v = b3[0]; sSum = 0.f; }
    __syncthreads();

    int warp = tid >> 5, lane = tid & 31;
    int half = lane >> 4, hl = lane & 15;
    int g = lane >> 2, tig = lane & 3;
    __half* xw = xs[warp];

    float4 bg = ((const float4*)b_gcn)[hl];   // loop-invariant
    float localSum = 0.f;

    for (;;) {
        unsigned grp;
        if (lane == 0) grp = atomicAdd(&g_work, 1u);
        grp = __shfl_sync(0xffffffffu, grp, 0);
        if (grp >= NGRP) break;
        int nodeBase = (int)grp * NTILE;

        // degrees for all 16 nodes (one coalesced load + shfl)
        int degAll = (lane < NTILE) ? __ldg(&g_cnt[nodeBase + lane]) : 0;

        // prefetch node 0's slot list
        int nextDeg = __shfl_sync(~0u, degAll, 0);
        int nextR = 0;
        {
            int c0 = nextDeg < 32 ? nextDeg : 32;
            if (lane < c0) nextR = __ldg(&g_slots[(size_t)nodeBase * CAP + lane]);
        }

        // ---- phase 1: gather 16 nodes into smem tile, slots prefetched ----
        for (int j = 0; j < NTILE; j++) {
            int node = nodeBase + j;
            int deg = nextDeg;
            int degc = deg < CAP ? deg : CAP;
            int r = nextR;

            if (j + 1 < NTILE) {
                nextDeg = __shfl_sync(~0u, degAll, j + 1);
                int cn = nextDeg < 32 ? nextDeg : 32;
                nextR = 0;
                if (lane < cn)
                    nextR = __ldg(&g_slots[(size_t)(node + 1) * CAP + lane]);
            }

            size_t nb = (size_t)node * CC;
            uint2 su = ((const uint2*)(g_xwh + nb))[hl];
            float4 st = ((const float4*)(state + nb))[hl];

            float4 acc = make_float4(0.f, 0.f, 0.f, 0.f);
            gather_batch(acc, r, degc < 32 ? degc : 32, half, hl);
            if (degc > 32) {                       // rare tail
                int r2 = 0;
                if (lane < degc - 32)
                    r2 = __ldg(&g_slots[(size_t)node * CAP + 32 + lane]);
                gather_batch(acc, r2, degc - 32, half, hl);
            }
            acc.x += __shfl_xor_sync(~0u, acc.x, 16);
            acc.y += __shfl_xor_sync(~0u, acc.y, 16);
            acc.z += __shfl_xor_sync(~0u, acc.z, 16);
            acc.w += __shfl_xor_sync(~0u, acc.w, 16);

            float dc = rsqrtf((float)(deg + 1));
            float2 s01 = __half22float2(*reinterpret_cast<__half2*>(&su.x));
            float2 s23 = __half22float2(*reinterpret_cast<__half2*>(&su.y));

            float xx = fmaxf(dc * (acc.x + s01.x) + bg.x, 0.f) + st.x;
            float xy = fmaxf(dc * (acc.y + s01.y) + bg.y, 0.f) + st.y;
            float xz = fmaxf(dc * (acc.z + s23.x) + bg.z, 0.f) + st.z;
            float xw2 = fmaxf(dc * (acc.w + s23.y) + bg.w, 0.f) + st.w;

            if (half == 0) {
                __half2 h01 = __floats2half2_rn(xx, xy);
                __half2 h23 = __floats2half2_rn(xz, xw2);
                uint2 pk = make_uint2(*(unsigned int*)&h01, *(unsigned int*)&h23);
                ((uint2*)(xw + j * XS))[hl] = pk;
            }
        }
        __syncwarp();

        // ---- phase 2: m16 HMMA MLP on own tile ----
        float acc1[4][4] = {};
        #pragma unroll
        for (int kt = 0; kt < 4; kt++) {
            unsigned ra[4];
            const __half* xr = xw + g * XS + kt * 16 + 2 * tig;
            ra[0] = *(const unsigned*)xr;
            ra[1] = *(const unsigned*)(xr + 8 * XS);
            ra[2] = *(const unsigned*)(xr + 8);
            ra[3] = *(const unsigned*)(xr + 8 * XS + 8);
            #pragma unroll
            for (int nt = 0; nt < 4; nt++) {
                const __half* wr = sW1t + (nt * 8 + g) * XS + kt * 16 + 2 * tig;
                mma16816(acc1[nt], ra, *(const unsigned*)wr, *(const unsigned*)(wr + 8));
            }
        }

        unsigned a2f[2][4];
        #pragma unroll
        for (int nt = 0; nt < 4; nt++) {
            float bc0 = sB1[nt * 8 + 2 * tig], bc1 = sB1[nt * 8 + 2 * tig + 1];
            float v0 = acc1[nt][0] + bc0, v1 = acc1[nt][1] + bc1;
            float v2 = acc1[nt][2] + bc0, v3 = acc1[nt][3] + bc1;
            v0 = fmaxf(v0, 0.01f * v0); v1 = fmaxf(v1, 0.01f * v1);
            v2 = fmaxf(v2, 0.01f * v2); v3 = fmaxf(v3, 0.01f * v3);
            __half2 p01 = __floats2half2_rn(v0, v1);
            __half2 p23 = __floats2half2_rn(v2, v3);
            int kt2 = nt >> 1, hi = nt & 1;
            a2f[kt2][hi ? 2 : 0] = *(unsigned*)&p01;
            a2f[kt2][hi ? 3 : 1] = *(unsigned*)&p23;
        }

        float acc2[4][4] = {};
        #pragma unroll
        for (int kt = 0; kt < 2; kt++) {
            #pragma unroll
            for (int nt = 0; nt < 4; nt++) {
                const __half* wr = sW2t + (nt * 8 + g) * 40 + kt * 16 + 2 * tig;
                mma16816(acc2[nt], a2f[kt], *(const unsigned*)wr, *(const unsigned*)(wr + 8));
            }
        }

        float p0 = 0.f, p1 = 0.f;
        #pragma unroll
        for (int nt = 0; nt < 4; nt++) {
            float bc0 = sB2[nt * 8 + 2 * tig], bc1 = sB2[nt * 8 + 2 * tig + 1];
            float w0 = sW3[nt * 8 + 2 * tig], w1 = sW3[nt * 8 + 2 * tig + 1];
            float c0 = acc2[nt][0] + bc0; c0 = fmaxf(c0, 0.01f * c0);
            float c1 = acc2[nt][1] + bc1; c1 = fmaxf(c1, 0.01f * c1);
            float c2 = acc2[nt][2] + bc0; c2 = fmaxf(c2, 0.01f * c2);
            float c3 = acc2[nt][3] + bc1; c3 = fmaxf(c3, 0.01f * c3);
            p0 += c0 * w0 + c1 * w1;
            p1 += c2 * w0 + c3 * w1;
        }
        p0 += __shfl_xor_sync(~0u, p0, 1); p0 += __shfl_xor_sync(~0u, p0, 2);
        p1 += __shfl_xor_sync(~0u, p1, 1); p1 += __shfl_xor_sync(~0u, p1, 2);
        if (tig == 0) {
            float z0 = p0 + sb3v;
            float c0v = (z0 > 20.f) ? z0 : log1pf(expf(z0));
            float z1 = p1 + sb3v;
            float c1v = (z1 > 20.f) ? z1 : log1pf(expf(z1));
            g_conc[nodeBase + g] = c0v;
            g_conc[nodeBase + g + 8] = c1v;
            localSum += c0v + c1v;
        }
        __syncwarp();   // xs reuse next iteration
    }

    localSum += __shfl_xor_sync(~0u, localSum, 1);
    localSum += __shfl_xor_sync(~0u, localSum, 2);
    localSum += __shfl_xor_sync(~0u, localSum, 4);
    localSum += __shfl_xor_sync(~0u, localSum, 8);
    localSum += __shfl_xor_sync(~0u, localSum, 16);
    if (lane == 0) atomicAdd(&sSum, localSum);
    __syncthreads();
    if (tid == 0) atomicAdd(&g_sum, sSum);
}

// ---------------------------------------------------------------------------
// action = conc / (sum + 1e-20); also re-zero g_cnt for the next replay
// ---------------------------------------------------------------------------
__global__ void k_norm(float* __restrict__ out) {
    int i = blockIdx.x * blockDim.x + threadIdx.x;
    if (i < NN / 4) {
        float inv = 1.0f / (g_sum + 1e-20f);
        float4 c = ((const float4*)g_conc)[i];
        ((float4*)out)[i] = make_float4(c.x * inv, c.y * inv, c.z * inv, c.w * inv);
        ((int4*)g_cnt)[i] = make_int4(0, 0, 0, 0);
    }
}

extern "C" void kernel_launch(void* const* d_in, const int* in_sizes, int n_in,
                              void* d_out, int out_size) {
    const float* state = (const float*)d_in[0];
    const int*   ei    = (const int*)d_in[1];
    const float* W_gcn = (const float*)d_in[2];
    const float* b_gcn = (const float*)d_in[3];
    const float* W1 = (const float*)d_in[4];
    const float* b1 = (const float*)d_in[5];
    const float* W2 = (const float*)d_in[6];
    const float* b2 = (const float*)d_in[7];
    const float* W3 = (const float*)d_in[8];
    const float* b3 = (const float*)d_in[9];
    float* out = (float*)d_out;

    k_bucket<<<(EE / 4 + 255) / 256, 256>>>(ei);
    k_gemm<<<NN / 64, 256>>>(state, W_gcn);
    k_fused<<<1184, 256>>>(state, b_gcn, W1, b1, W2, b2, W3, b3);
    k_norm<<<NN / 4 / 256, 256>>>(out);
}